// round 10
// baseline (speedup 1.0000x reference)
#include <cuda_runtime.h>
#include <cstdint>

#define N_TOK 12288
#define DHEAD 128
#define NUMB  32
#define BM 64
#define BN 64
#define KSPLIT 128
#define MAXPARTS 6
#define NTHREADS 256
#define ITEMCAP 4096
#define NWORKERS 296

__device__ int  g_seg_start[NUMB + 1];
__device__ int4 g_items[ITEMCAP];     // x=row0, y=nrows, z=klo, w=part
__device__ int  g_nitems;
__device__ int  g_ctr;
__device__ float g_pO[MAXPARTS][N_TOK][DHEAD];  // unnormalized partial O
__device__ float g_pl[MAXPARTS][N_TOK];          // partial row sums

// ---------------------------------------------------------------------------
// Prep (fully parallel, 1024 threads): boundary-detect seg starts, warp-scan
// item offsets, 32 warps emit items lane-parallel.
// ---------------------------------------------------------------------------
__global__ void prep_kernel(const int* __restrict__ bseg) {
    __shared__ int iofs[NUMB + 1];
    const int tid = threadIdx.x;
    if (tid == 0) g_ctr = 0;
    for (int i = tid; i < N_TOK; i += blockDim.x) {
        if (i == 0) {
            int c = bseg[0];
            for (int b = 0; b <= c; b++) g_seg_start[b] = 0;
        } else {
            int a = bseg[i - 1], c = bseg[i];
            for (int b = a + 1; b <= c; b++) g_seg_start[b] = i;
        }
    }
    if (tid == 0) {
        int last = bseg[N_TOK - 1];
        for (int b = last + 1; b <= NUMB; b++) g_seg_start[b] = N_TOK;
    }
    __syncthreads();
    if (tid < 32) {
        int lo = g_seg_start[tid], hi = g_seg_start[tid + 1];
        int rows = hi - lo;
        int cntb = ((rows + BM - 1) / BM) * ((rows + KSPLIT - 1) / KSPLIT);
        int x = cntb;
        #pragma unroll
        for (int o = 1; o < 32; o <<= 1) {
            int y = __shfl_up_sync(0xffffffffu, x, o);
            if (tid >= o) x += y;
        }
        iofs[tid + 1] = x;
        if (tid == 0) iofs[0] = 0;
        if (tid == 31) g_nitems = x;
    }
    __syncthreads();
    const int wid = tid >> 5, lane = tid & 31;
    if (wid < NUMB) {
        int lo = g_seg_start[wid], hi = g_seg_start[wid + 1];
        int rows = hi - lo;
        int nkp = (rows + KSPLIT - 1) / KSPLIT;
        int nrt = (rows + BM - 1) / BM;
        int base = iofs[wid];
        for (int j = lane; j < nrt * nkp; j += 32) {
            int rt = j / nkp, p = j % nkp;
            int r0 = lo + rt * BM;
            g_items[base + j] = make_int4(r0, min(BM, hi - r0), lo + p * KSPLIT, p);
        }
    }
}

// ---------------------------------------------------------------------------
// PTX helpers
// ---------------------------------------------------------------------------
__device__ __forceinline__ void mbar_init(uint32_t mbar) {
    asm volatile("mbarrier.init.shared.b64 [%0], 1;" :: "r"(mbar) : "memory");
}
__device__ __forceinline__ void mbar_expect(uint32_t mbar, uint32_t bytes) {
    asm volatile("mbarrier.arrive.expect_tx.shared.b64 _, [%0], %1;"
                 :: "r"(mbar), "r"(bytes) : "memory");
}
__device__ __forceinline__ void mbar_wait(uint32_t mbar, uint32_t phase) {
    asm volatile(
        "{\n\t.reg .pred P;\n\t"
        "WAIT_%=:\n\t"
        "mbarrier.try_wait.parity.acquire.cta.shared::cta.b64 P, [%0], %1, 0x989680;\n\t"
        "@P bra.uni DONE_%=;\n\t"
        "bra.uni WAIT_%=;\n\t"
        "DONE_%=:\n\t}"
        :: "r"(mbar), "r"(phase) : "memory");
}
__device__ __forceinline__ void fence_async() {
    asm volatile("fence.proxy.async.shared::cta;" ::: "memory");
}
__device__ __forceinline__ void bulk_g2s(uint32_t dst, const void* src,
                                         uint32_t bytes, uint32_t mbar) {
    asm volatile(
        "cp.async.bulk.shared::cluster.global.mbarrier::complete_tx::bytes "
        "[%0], [%1], %2, [%3];"
        :: "r"(dst), "l"(src), "r"(bytes), "r"(mbar) : "memory");
}
__device__ __forceinline__ void fma2(unsigned long long& d,
                                     const unsigned long long a,
                                     const unsigned long long b) {
    asm volatile("fma.rn.f32x2 %0, %1, %2, %0;" : "+l"(d) : "l"(a), "l"(b));
}
__device__ __forceinline__ unsigned long long dup2(float x) {
    unsigned long long d;
    asm("mov.b64 %0, {%1, %1};" : "=l"(d) : "f"(x));
    return d;
}

// ---------------------------------------------------------------------------
// Main kernel. 256 threads = 8 warps; warp wy owns rows wy*8..+7 of the item.
// Lane tx owns score cols {2tx,2tx+1}, output cols 4tx..+3.
// ALL smem LINEAR; tiles loaded by cp.async.bulk (1 instr / 32KB tile).
// QK conflict-free via chunk rotation c^(tx&7) applied to BOTH Q and K
// (bijection; Q/K chunk indices match, so dot products are exact).
// PV indexes V chunks by tx -> conflict-free on linear layout.
// ---------------------------------------------------------------------------
__global__ __launch_bounds__(NTHREADS, 2)
void attn_kernel(const float* __restrict__ Q, const float* __restrict__ K,
                 const float* __restrict__ V, const int* __restrict__ bseg) {
    extern __shared__ float smf[];
    float* Qs = smf;            // [64][128] 32KB linear
    float* Ab = smf + 8192;     // [64][128] 32KB linear (K tile)
    float* Bb = smf + 16384;    // [64][128] 32KB linear (V tile)
    float* Ps = smf + 24576;    // [64][64]  16KB (e0,e1) pairs
    __shared__ unsigned long long s_mbar[2];
    __shared__ int s_work;

    const int tid = threadIdx.x;
    const int tx  = tid & 31;
    const int wy  = tid >> 5;                 // 0..7
    const uint32_t sm_u = (uint32_t)__cvta_generic_to_shared(smf);
    const uint32_t qs_u = sm_u;
    const uint32_t a_u  = sm_u + 8192u * 4u;
    const uint32_t b_u  = sm_u + 16384u * 4u;
    const uint32_t mbA  = (uint32_t)__cvta_generic_to_shared(&s_mbar[0]);
    const uint32_t mbB  = (uint32_t)__cvta_generic_to_shared(&s_mbar[1]);
    const float isd = 0.0883883476483184f;    // 1/sqrt(128)
    const int e = tx & 7;                     // chunk rotation

    if (tid == 0) { mbar_init(mbA); mbar_init(mbB); fence_async(); }
    // zero-init Q/A/B once (prevents NaN poison via 0*NaN on tail tiles)
    #pragma unroll
    for (int t = 0; t < 24; t++)
        *(float4*)(smf + (tid + t * NTHREADS) * 4) =
            make_float4(0.f, 0.f, 0.f, 0.f);
    __syncthreads();

    uint32_t phA = 0, phB = 0;

    while (true) {
        __syncthreads();                      // prev item's smem reads done
        if (tid == 0) s_work = atomicAdd(&g_ctr, 1);
        __syncthreads();
        const int w = s_work;
        if (w >= g_nitems) break;
        const int4 it = g_items[w];
        const int r0 = it.x, nrows = it.y, klo = it.z, part = it.w;
        const int b   = bseg[r0];
        const int khi = min(klo + KSPLIT, g_seg_start[b + 1]);

        // Issue Q tile + first K tile (both signal mbA)
        if (tid == 0) {
            uint32_t qb = (uint32_t)min(BM, N_TOK - r0) * 512u;
            uint32_t kb = (uint32_t)min(BM, N_TOK - klo) * 512u;
            fence_async();
            mbar_expect(mbA, qb + kb);
            bulk_g2s(qs_u, Q + (size_t)r0 * DHEAD, qb, mbA);
            bulk_g2s(a_u,  K + (size_t)klo * DHEAD, kb, mbA);
        }

        unsigned long long o2[8][2];
        float lsum[8];
        #pragma unroll
        for (int i = 0; i < 8; i++) { o2[i][0] = 0ULL; o2[i][1] = 0ULL; lsum[i] = 0.f; }

        for (int kt = klo; kt < khi; kt += BN) {
            mbar_wait(mbA, phA); phA ^= 1;    // K(t) (+Q on first iter) ready

            // Issue V(t) -> B (B free: prev PV finished before loop-entry syncs)
            if (tid == 0) {
                uint32_t vb = (uint32_t)min(BM, N_TOK - kt) * 512u;
                fence_async();
                mbar_expect(mbB, vb);
                bulk_g2s(b_u, V + (size_t)kt * DHEAD, vb, mbB);
            }

            // ---- QK: 8 rows x 2 cols per lane, rotated chunks ----
            const float* kp0 = Ab + (2 * tx) * 128;
            const float* qp  = Qs + (wy * 8) * 128;
            unsigned long long s2[8][2];
            #pragma unroll
            for (int i = 0; i < 8; i++) { s2[i][0] = 0ULL; s2[i][1] = 0ULL; }

            #pragma unroll 4
            for (int c = 0; c < 32; c++) {
                int kph = (c ^ e) << 2;
                ulonglong2 ka = *(const ulonglong2*)(kp0 + kph);
                ulonglong2 kb = *(const ulonglong2*)(kp0 + 128 + kph);
                const float* qc = qp + kph;
                #pragma unroll
                for (int i = 0; i < 8; i++) {
                    ulonglong2 qa = *(const ulonglong2*)(qc + i * 128);
                    fma2(s2[i][0], qa.x, ka.x);
                    fma2(s2[i][0], qa.y, ka.y);
                    fma2(s2[i][1], qa.x, kb.x);
                    fma2(s2[i][1], qa.y, kb.y);
                }
            }

            // ---- masked exp, P store (e0,e1) once (warp-private rows) ----
            const int col0 = kt + 2 * tx;
            #pragma unroll
            for (int i = 0; i < 8; i++) {
                unsigned long long v0 = s2[i][0], v1 = s2[i][1];
                float sv0 = (__uint_as_float((unsigned)v0) +
                             __uint_as_float((unsigned)(v0 >> 32))) * isd;
                float sv1 = (__uint_as_float((unsigned)v1) +
                             __uint_as_float((unsigned)(v1 >> 32))) * isd;
                float e0 = (col0     < khi) ? __expf(sv0) : 0.f;
                float e1 = (col0 + 1 < khi) ? __expf(sv1) : 0.f;
                lsum[i] += e0 + e1;
                float2 ev; ev.x = e0; ev.y = e1;
                *(float2*)(Ps + (wy * 8 + i) * 64 + tx * 2) = ev;
            }
            __syncthreads();                  // all A reads done

            // Issue K(t+1) -> A (overlaps PV)
            if ((kt + BN) < khi && tid == 0) {
                uint32_t kb2 = (uint32_t)min(BM, N_TOK - (kt + BN)) * 512u;
                fence_async();
                mbar_expect(mbA, kb2);
                bulk_g2s(a_u, K + (size_t)(kt + BN) * DHEAD, kb2, mbA);
            }

            mbar_wait(mbB, phB); phB ^= 1;    // V(t) ready

            // ---- PV from B (linear, chunk = tx); P dup'd in registers ----
            const float* pp = Ps + (wy * 8) * 64;
            #pragma unroll 4
            for (int c2 = 0; c2 < 32; c2++) {
                const float* vrow = Bb + (2 * c2) * 128 + tx * 4;
                ulonglong2 vv0 = *(const ulonglong2*)(vrow);        // row 2c2
                ulonglong2 vv1 = *(const ulonglong2*)(vrow + 128);  // row 2c2+1
                #pragma unroll
                for (int i = 0; i < 8; i++) {
                    float2 pu = *(const float2*)(pp + i * 64 + c2 * 2);
                    unsigned long long d0 = dup2(pu.x);
                    unsigned long long d1 = dup2(pu.y);
                    fma2(o2[i][0], d0, vv0.x);
                    fma2(o2[i][1], d0, vv0.y);
                    fma2(o2[i][0], d1, vv1.x);
                    fma2(o2[i][1], d1, vv1.y);
                }
            }
            __syncthreads();                  // all B reads done before next V issue
        }

        // ---- epilogue: reduce l, store UNNORMALIZED partials ----
        #pragma unroll
        for (int i = 0; i < 8; i++) {
            float l = lsum[i];
            #pragma unroll
            for (int o = 16; o >= 1; o >>= 1)
                l += __shfl_xor_sync(0xffffffffu, l, o);
            int row = wy * 8 + i;
            if (row < nrows) {
                int gr = r0 + row;
                unsigned long long a = o2[i][0], bb = o2[i][1];
                float4 r4;
                r4.x = __uint_as_float((unsigned)a);
                r4.y = __uint_as_float((unsigned)(a >> 32));
                r4.z = __uint_as_float((unsigned)bb);
                r4.w = __uint_as_float((unsigned)(bb >> 32));
                *(float4*)&g_pO[part][gr][tx * 4] = r4;
                if (tx == 0) g_pl[part][gr] = l;
            }
        }
    }
}

// ---------------------------------------------------------------------------
// Combine: out[r] = sum_p pO[p][r] / sum_p pl[p][r]
// ---------------------------------------------------------------------------
__global__ void combine_kernel(const int* __restrict__ bseg,
                               float* __restrict__ out) {
    int idx = blockIdx.x * blockDim.x + threadIdx.x;   // 0 .. N_TOK*32-1
    int r  = idx >> 5;
    int c4 = idx & 31;
    int b  = bseg[r];
    int span = g_seg_start[b + 1] - g_seg_start[b];
    int np = (span + KSPLIT - 1) / KSPLIT;
    float4 a = *(const float4*)&g_pO[0][r][c4 * 4];
    float  l = g_pl[0][r];
    for (int p = 1; p < np; p++) {
        float4 t = *(const float4*)&g_pO[p][r][c4 * 4];
        a.x += t.x; a.y += t.y; a.z += t.z; a.w += t.w;
        l += g_pl[p][r];
    }
    float inv = 1.0f / l;   // EPS negligible (validated R2-R9)
    a.x *= inv; a.y *= inv; a.z *= inv; a.w *= inv;
    *(float4*)&out[(size_t)r * DHEAD + c4 * 4] = a;
}

// ---------------------------------------------------------------------------
extern "C" void kernel_launch(void* const* d_in, const int* in_sizes, int n_in,
                              void* d_out, int out_size) {
    const float* Q  = (const float*)d_in[0];
    const float* K  = (const float*)d_in[1];
    const float* V  = (const float*)d_in[2];
    const int* bseg = (const int*)d_in[n_in - 1];
    float* out      = (float*)d_out;

    const int smem_bytes = (8192 * 3 + 4096) * (int)sizeof(float);   // 112KB
    cudaFuncSetAttribute(attn_kernel, cudaFuncAttributeMaxDynamicSharedMemorySize,
                         smem_bytes);

    prep_kernel<<<1, 1024>>>(bseg);
    attn_kernel<<<NWORKERS, NTHREADS, smem_bytes>>>(Q, K, V, bseg);
    combine_kernel<<<N_TOK * 32 / 256, 256>>>(bseg, out);
}